// round 1
// baseline (speedup 1.0000x reference)
#include <cuda_runtime.h>
#include <math.h>

// Problem constants
#define B_   2
#define S_   2048
#define D_   2048
#define H_   16
#define KV_  4
#define KQD_ 96
#define VD_  128
#define TOK  (B_*S_)       // 4096 tokens
#define QN   (H_*KQD_)     // 1536
#define KN   (KV_*KQD_)    // 384
#define VN   (KV_*VD_)     // 512
#define ON   (H_*VD_)      // 2048

// Scratch (device globals; allocation APIs are forbidden)
__device__ float g_q [TOK * QN];      // 24 MB
__device__ float g_k [TOK * KN];      //  6 MB
__device__ float g_v [TOK * VN];      //  8 MB
__device__ float g_ao[TOK * ON];      // 32 MB
__device__ float g_cos[S_ * 48];
__device__ float g_sin[S_ * 48];

// ---------------------------------------------------------------------------
// RoPE table: cos/sin computed in double (safe vs fast-math sinf at large args)
// ---------------------------------------------------------------------------
__global__ void rope_table_kernel() {
    int i = blockIdx.x * blockDim.x + threadIdx.x;
    if (i >= S_ * 48) return;
    int pos = i / 48, j = i % 48;
    double inv = exp(-log(10000.0) * (double)j / 48.0);
    double ang = (double)pos * inv;
    g_cos[i] = (float)cos(ang);
    g_sin[i] = (float)sin(ang);
}

// ---------------------------------------------------------------------------
// SGEMM-NT: C[M,N] = A[M,K] * B[N,K]^T   (all row-major, dims % 128 == 0, K%8==0)
// 128x128 tile, BK=8, 256 threads, 8x8 micro-tile with 4+4 split columns.
// ---------------------------------------------------------------------------
__global__ void __launch_bounds__(256) sgemm_nt(
    const float* __restrict__ A, const float* __restrict__ Bm,
    float* __restrict__ C, int M, int N, int K)
{
    __shared__ float As[8][128];
    __shared__ float Bs[8][128];
    const int tid = threadIdx.x;
    const int bm  = blockIdx.y << 7;
    const int bn  = blockIdx.x << 7;
    const int lr  = tid >> 1;           // 0..127
    const int lc  = (tid & 1) << 2;     // 0 or 4
    const float* Ap = A  + (size_t)(bm + lr) * K + lc;
    const float* Bp = Bm + (size_t)(bn + lr) * K + lc;
    const int tx = tid & 15;
    const int ty = tid >> 4;

    float acc[8][8];
#pragma unroll
    for (int i = 0; i < 8; i++)
#pragma unroll
        for (int j = 0; j < 8; j++) acc[i][j] = 0.f;

    for (int k0 = 0; k0 < K; k0 += 8) {
        float4 a4 = *(const float4*)(Ap + k0);
        float4 b4 = *(const float4*)(Bp + k0);
        As[lc+0][lr] = a4.x; As[lc+1][lr] = a4.y; As[lc+2][lr] = a4.z; As[lc+3][lr] = a4.w;
        Bs[lc+0][lr] = b4.x; Bs[lc+1][lr] = b4.y; Bs[lc+2][lr] = b4.z; Bs[lc+3][lr] = b4.w;
        __syncthreads();
#pragma unroll
        for (int kk = 0; kk < 8; kk++) {
            float4 a0 = *(const float4*)&As[kk][ty * 4];
            float4 a1 = *(const float4*)&As[kk][64 + ty * 4];
            float4 b0 = *(const float4*)&Bs[kk][tx * 4];
            float4 b1 = *(const float4*)&Bs[kk][64 + tx * 4];
            float ar[8] = {a0.x,a0.y,a0.z,a0.w,a1.x,a1.y,a1.z,a1.w};
            float br[8] = {b0.x,b0.y,b0.z,b0.w,b1.x,b1.y,b1.z,b1.w};
#pragma unroll
            for (int i = 0; i < 8; i++)
#pragma unroll
                for (int j = 0; j < 8; j++)
                    acc[i][j] += ar[i] * br[j];
        }
        __syncthreads();
    }

#pragma unroll
    for (int i = 0; i < 8; i++) {
        int row = bm + ((i < 4) ? (ty * 4 + i) : (64 + ty * 4 + (i - 4)));
        float4 c0 = make_float4(acc[i][0], acc[i][1], acc[i][2], acc[i][3]);
        float4 c1 = make_float4(acc[i][4], acc[i][5], acc[i][6], acc[i][7]);
        *(float4*)&C[(size_t)row * N + bn + tx * 4]      = c0;
        *(float4*)&C[(size_t)row * N + bn + 64 + tx * 4] = c1;
    }
}

// ---------------------------------------------------------------------------
// Fused RMSNorm + RoPE, in place. One warp per (token, head) row of 96.
// ---------------------------------------------------------------------------
__global__ void rmsnorm_rope_kernel(float* buf, const float* __restrict__ w,
                                    const int* __restrict__ pos_ids,
                                    int heads, int R)
{
    __shared__ float sh[4][96];
    const int wid  = threadIdx.x >> 5;
    const int lane = threadIdx.x & 31;
    const int row  = blockIdx.x * 4 + wid;
    if (row >= R) return;
    const int token = row / heads;
    float* x = buf + (size_t)row * 96;

    float v0 = x[lane], v1 = x[lane + 32], v2 = x[lane + 64];
    float ss = v0 * v0 + v1 * v1 + v2 * v2;
#pragma unroll
    for (int o = 16; o; o >>= 1) ss += __shfl_xor_sync(0xffffffffu, ss, o);
    float inv = rsqrtf(ss * (1.0f / 96.0f) + 1e-6f);

    sh[wid][lane]      = v0 * inv * w[lane];
    sh[wid][lane + 32] = v1 * inv * w[lane + 32];
    sh[wid][lane + 64] = v2 * inv * w[lane + 64];
    __syncwarp();

    const int pos = pos_ids[token];
    const float* ct = g_cos + pos * 48;
    const float* st = g_sin + pos * 48;
#pragma unroll
    for (int q3 = 0; q3 < 3; q3++) {
        int d = lane + q3 * 32;
        int f = (d < 48) ? d : d - 48;
        float rh = (d < 48) ? -sh[wid][d + 48] : sh[wid][d - 48];
        x[d] = sh[wid][d] * ct[f] + rh * st[f];
    }
}

// ---------------------------------------------------------------------------
// Flash attention (fp32, causal, GQA 4:1). CTA = (q-tile of 32, head, batch),
// 128 threads. Online softmax; causal tiles beyond diagonal skipped.
// Shared layouts padded for conflict-free compute-phase LDS.
// ---------------------------------------------------------------------------
__global__ void __launch_bounds__(128) attn_kernel()
{
    const int qt  = blockIdx.x;       // 0..63
    const int h   = blockIdx.y;       // 0..15
    const int b   = blockIdx.z;       // 0..1
    const int kvh = h >> 2;
    const int t   = threadIdx.x;

    __shared__ float Qs[32][97];
    __shared__ float KsT[96][33];
    __shared__ float Vs[32][128];
    __shared__ float Ss[32][33];
    __shared__ float rowm[32], rowl[32], alphas[32];

    // Load Q tile
    const float* qptr = g_q + ((size_t)(b * S_ + qt * 32)) * QN + h * KQD_;
    for (int i = t; i < 32 * 96; i += 128) {
        int r = i / 96, kk = i % 96;
        Qs[r][kk] = qptr[(size_t)r * QN + kk];
    }
    if (t < 32) { rowm[t] = -INFINITY; rowl[t] = 0.f; }

    float O[4][8];
#pragma unroll
    for (int i = 0; i < 4; i++)
#pragma unroll
        for (int j = 0; j < 8; j++) O[i][j] = 0.f;

    const int ra  = t >> 3;           // S rows: ra, ra+16
    const int jc0 = (t & 7) * 4;      // S cols: jc0..jc0+3
    const int rg  = t >> 4;           // O rows: rg + 8*ri
    const int cl  = t & 15;           // O cols: cl + 16*ci
    const float scale = 1.0f / sqrtf(96.0f);

    for (int kt = 0; kt <= qt; kt++) {
        __syncthreads();  // prev O-update done with Ss/Vs
        // Load K tile transposed + V tile
        const float* kptr = g_k + ((size_t)(b * S_ + kt * 32)) * KN + kvh * KQD_;
        for (int i = t; i < 32 * 96; i += 128) {
            int j = i / 96, kk = i % 96;
            KsT[kk][j] = kptr[(size_t)j * KN + kk];
        }
        const float* vptr = g_v + ((size_t)(b * S_ + kt * 32)) * VN + kvh * VD_;
        for (int i = t; i < 32 * 128; i += 128) {
            int j = i >> 7, c = i & 127;
            Vs[j][c] = vptr[(size_t)j * VN + c];
        }
        __syncthreads();

        // S = Q K^T
        float a0[4] = {0,0,0,0}, a1[4] = {0,0,0,0};
#pragma unroll 8
        for (int kk = 0; kk < 96; kk++) {
            float q0 = Qs[ra][kk], q1 = Qs[ra + 16][kk];
#pragma unroll
            for (int jj = 0; jj < 4; jj++) {
                float kvv = KsT[kk][jc0 + jj];
                a0[jj] += q0 * kvv;
                a1[jj] += q1 * kvv;
            }
        }
        const bool diag = (kt == qt);
#pragma unroll
        for (int jj = 0; jj < 4; jj++) {
            int j = jc0 + jj;
            float s0 = a0[jj] * scale, s1 = a1[jj] * scale;
            if (diag) {
                if (j > ra)      s0 = -INFINITY;
                if (j > ra + 16) s1 = -INFINITY;
            }
            Ss[ra][j]      = s0;
            Ss[ra + 16][j] = s1;
        }
        __syncthreads();

        // Online softmax update (4 lanes per row)
        {
            int row = t >> 2, sub = t & 3;
            float pv[8], mloc = -INFINITY;
#pragma unroll
            for (int i2 = 0; i2 < 8; i2++) {
                pv[i2] = Ss[row][sub * 8 + i2];
                mloc = fmaxf(mloc, pv[i2]);
            }
            mloc = fmaxf(mloc, __shfl_xor_sync(0xffffffffu, mloc, 1));
            mloc = fmaxf(mloc, __shfl_xor_sync(0xffffffffu, mloc, 2));
            float mold = rowm[row];
            float mnew = fmaxf(mold, mloc);
            float sum = 0.f;
#pragma unroll
            for (int i2 = 0; i2 < 8; i2++) {
                float p = __expf(pv[i2] - mnew);
                sum += p;
                Ss[row][sub * 8 + i2] = p;
            }
            sum += __shfl_xor_sync(0xffffffffu, sum, 1);
            sum += __shfl_xor_sync(0xffffffffu, sum, 2);
            if (sub == 0) {
                float alpha = __expf(mold - mnew);   // 0 on first tile
                rowm[row]   = mnew;
                rowl[row]   = rowl[row] * alpha + sum;
                alphas[row] = alpha;
            }
        }
        __syncthreads();

        // O = alpha*O + P V
#pragma unroll
        for (int ri = 0; ri < 4; ri++) {
            float a = alphas[rg + 8 * ri];
#pragma unroll
            for (int ci = 0; ci < 8; ci++) O[ri][ci] *= a;
        }
#pragma unroll 4
        for (int j = 0; j < 32; j++) {
            float p0 = Ss[rg][j], p1 = Ss[rg + 8][j];
            float p2 = Ss[rg + 16][j], p3 = Ss[rg + 24][j];
#pragma unroll
            for (int ci = 0; ci < 8; ci++) {
                float v = Vs[j][cl + (ci << 4)];
                O[0][ci] += p0 * v;
                O[1][ci] += p1 * v;
                O[2][ci] += p2 * v;
                O[3][ci] += p3 * v;
            }
        }
    }

    // Epilogue: O /= l, write [token, h*128 + col]
    float* optr = g_ao + ((size_t)(b * S_ + qt * 32)) * ON + h * VD_;
#pragma unroll
    for (int ri = 0; ri < 4; ri++) {
        int r = rg + 8 * ri;
        float invl = 1.0f / rowl[r];
#pragma unroll
        for (int ci = 0; ci < 8; ci++)
            optr[(size_t)r * ON + cl + (ci << 4)] = O[ri][ci] * invl;
    }
}

// ---------------------------------------------------------------------------
extern "C" void kernel_launch(void* const* d_in, const int* in_sizes, int n_in,
                              void* d_out, int out_size)
{
    const float* hidden = (const float*)d_in[0];
    const int*   pos    = (const int*)  d_in[1];
    const float* Wq     = (const float*)d_in[2];
    const float* Wk     = (const float*)d_in[3];
    const float* Wv     = (const float*)d_in[4];
    const float* Wo     = (const float*)d_in[5];
    const float* qw     = (const float*)d_in[6];
    const float* kw     = (const float*)d_in[7];
    float* out = (float*)d_out;

    void *pq, *pk, *pv, *pa;
    cudaGetSymbolAddress(&pq, g_q);
    cudaGetSymbolAddress(&pk, g_k);
    cudaGetSymbolAddress(&pv, g_v);
    cudaGetSymbolAddress(&pa, g_ao);
    float* qb = (float*)pq;
    float* kb = (float*)pk;
    float* vb = (float*)pv;
    float* ab = (float*)pa;

    // 1. RoPE table
    rope_table_kernel<<<(S_ * 48 + 255) / 256, 256>>>();

    // 2. QKV projections
    sgemm_nt<<<dim3(QN / 128, TOK / 128), 256>>>(hidden, Wq, qb, TOK, QN, D_);
    sgemm_nt<<<dim3(KN / 128, TOK / 128), 256>>>(hidden, Wk, kb, TOK, KN, D_);
    sgemm_nt<<<dim3(VN / 128, TOK / 128), 256>>>(hidden, Wv, vb, TOK, VN, D_);

    // 3. RMSNorm + RoPE (in place)
    rmsnorm_rope_kernel<<<(TOK * H_) / 4, 128>>>(qb, qw, pos, H_, TOK * H_);
    rmsnorm_rope_kernel<<<(TOK * KV_) / 4, 128>>>(kb, kw, pos, KV_, TOK * KV_);

    // 4. Attention
    attn_kernel<<<dim3(S_ / 32, H_, B_), 128>>>();

    // 5. Output projection
    sgemm_nt<<<dim3(D_ / 128, TOK / 128), 256>>>(ab, Wo, out, TOK, D_, ON);
}

// round 2
// speedup vs baseline: 1.5940x; 1.5940x over previous
#include <cuda_runtime.h>
#include <math.h>

// Problem constants
#define B_   2
#define S_   2048
#define D_   2048
#define H_   16
#define KV_  4
#define KQD_ 96
#define VD_  128
#define TOK  (B_*S_)       // 4096 tokens
#define QN   (H_*KQD_)     // 1536
#define KN   (KV_*KQD_)    // 384
#define VN   (KV_*VD_)     // 512
#define ON   (H_*VD_)      // 2048

// Scratch (device globals; allocation APIs are forbidden)
__device__ float g_q [TOK * QN];      // 24 MB
__device__ float g_k [TOK * KN];      //  6 MB
__device__ float g_v [TOK * VN];      //  8 MB
__device__ float g_ao[TOK * ON];      // 32 MB
__device__ float g_cos[S_ * 48];
__device__ float g_sin[S_ * 48];

// ---------------------------------------------------------------------------
// RoPE table: cos/sin computed in double (safe vs fast-math sinf at large args)
// ---------------------------------------------------------------------------
__global__ void rope_table_kernel() {
    int i = blockIdx.x * blockDim.x + threadIdx.x;
    if (i >= S_ * 48) return;
    int pos = i / 48, j = i % 48;
    double inv = exp(-log(10000.0) * (double)j / 48.0);
    double ang = (double)pos * inv;
    g_cos[i] = (float)cos(ang);
    g_sin[i] = (float)sin(ang);
}

// ---------------------------------------------------------------------------
// TF32 tensor-core GEMM-NT: C[M,N] = A[M,K] * B[N,K]^T  (row-major)
// Requires M%128==0, N%128==0, K%16==0.
// 128x128 CTA tile, BK=16 double-buffered, 8 warps of 64x32,
// mma.sync.m16n8k8 tf32. Smem k-major with stride 136 (conflict-free frags).
// ---------------------------------------------------------------------------
#define BKT 16
#define SSTR 136   // 136 % 32 == 8 -> frag loads hit all banks once

__device__ __forceinline__ unsigned f2tf32(float x) {
    unsigned r;
    asm("cvt.rna.tf32.f32 %0, %1;" : "=r"(r) : "f"(x));
    return r;
}

__device__ __forceinline__ void mma_tf32(float* c, const unsigned* a, const unsigned* b) {
    asm volatile(
        "mma.sync.aligned.m16n8k8.row.col.f32.tf32.tf32.f32 "
        "{%0,%1,%2,%3}, {%4,%5,%6,%7}, {%8,%9}, {%0,%1,%2,%3};\n"
        : "+f"(c[0]), "+f"(c[1]), "+f"(c[2]), "+f"(c[3])
        : "r"(a[0]), "r"(a[1]), "r"(a[2]), "r"(a[3]),
          "r"(b[0]), "r"(b[1]));
}

__global__ void __launch_bounds__(256) sgemm_tf32(
    const float* __restrict__ A, const float* __restrict__ Bm,
    float* __restrict__ C, int M, int N, int K)
{
    __shared__ unsigned As[2][BKT][SSTR];
    __shared__ unsigned Bs[2][BKT][SSTR];

    const int tid  = threadIdx.x;
    const int bm   = blockIdx.y << 7;
    const int bn   = blockIdx.x << 7;
    const int warp = tid >> 5;
    const int lane = tid & 31;
    const int g    = lane >> 2;     // 0..7
    const int t    = lane & 3;      // 0..3
    const int wm   = (warp >> 2) * 64;   // 0 or 64
    const int wn   = (warp & 3) * 32;    // 0,32,64,96

    // gmem load mapping: 256 threads cover 128 rows x 16 k (8 floats each)
    const int lrow = tid >> 1;           // 0..127
    const int lkc  = (tid & 1) * 8;      // 0 or 8
    const float* Ap = A  + (size_t)(bm + lrow) * K + lkc;
    const float* Bp = Bm + (size_t)(bn + lrow) * K + lkc;

    float acc[4][4][4];
#pragma unroll
    for (int i = 0; i < 4; i++)
#pragma unroll
        for (int j = 0; j < 4; j++)
#pragma unroll
            for (int r = 0; r < 4; r++) acc[i][j][r] = 0.f;

    // preload stage 0
    float4 pa0 = *(const float4*)(Ap + 0);
    float4 pa1 = *(const float4*)(Ap + 4);
    float4 pb0 = *(const float4*)(Bp + 0);
    float4 pb1 = *(const float4*)(Bp + 4);
    {
        As[0][lkc+0][lrow] = f2tf32(pa0.x); As[0][lkc+1][lrow] = f2tf32(pa0.y);
        As[0][lkc+2][lrow] = f2tf32(pa0.z); As[0][lkc+3][lrow] = f2tf32(pa0.w);
        As[0][lkc+4][lrow] = f2tf32(pa1.x); As[0][lkc+5][lrow] = f2tf32(pa1.y);
        As[0][lkc+6][lrow] = f2tf32(pa1.z); As[0][lkc+7][lrow] = f2tf32(pa1.w);
        Bs[0][lkc+0][lrow] = f2tf32(pb0.x); Bs[0][lkc+1][lrow] = f2tf32(pb0.y);
        Bs[0][lkc+2][lrow] = f2tf32(pb0.z); Bs[0][lkc+3][lrow] = f2tf32(pb0.w);
        Bs[0][lkc+4][lrow] = f2tf32(pb1.x); Bs[0][lkc+5][lrow] = f2tf32(pb1.y);
        Bs[0][lkc+6][lrow] = f2tf32(pb1.z); Bs[0][lkc+7][lrow] = f2tf32(pb1.w);
    }
    __syncthreads();

    int cur = 0;
    for (int k0 = BKT; k0 <= K; k0 += BKT) {
        const bool more = (k0 < K);
        if (more) {
            pa0 = *(const float4*)(Ap + k0);
            pa1 = *(const float4*)(Ap + k0 + 4);
            pb0 = *(const float4*)(Bp + k0);
            pb1 = *(const float4*)(Bp + k0 + 4);
        }

        // compute both k8 halves from stage `cur`
#pragma unroll
        for (int kh = 0; kh < 2; kh++) {
            const int k8 = kh * 8;
            unsigned af[4][4], bf[4][2];
#pragma unroll
            for (int i = 0; i < 4; i++) {
                int m = wm + 16 * i;
                af[i][0] = As[cur][k8 + t    ][m + g];
                af[i][1] = As[cur][k8 + t    ][m + g + 8];
                af[i][2] = As[cur][k8 + t + 4][m + g];
                af[i][3] = As[cur][k8 + t + 4][m + g + 8];
            }
#pragma unroll
            for (int j = 0; j < 4; j++) {
                int n = wn + 8 * j;
                bf[j][0] = Bs[cur][k8 + t    ][n + g];
                bf[j][1] = Bs[cur][k8 + t + 4][n + g];
            }
#pragma unroll
            for (int i = 0; i < 4; i++)
#pragma unroll
                for (int j = 0; j < 4; j++)
                    mma_tf32(acc[i][j], af[i], bf[j]);
        }

        if (more) {
            int nxt = cur ^ 1;
            As[nxt][lkc+0][lrow] = f2tf32(pa0.x); As[nxt][lkc+1][lrow] = f2tf32(pa0.y);
            As[nxt][lkc+2][lrow] = f2tf32(pa0.z); As[nxt][lkc+3][lrow] = f2tf32(pa0.w);
            As[nxt][lkc+4][lrow] = f2tf32(pa1.x); As[nxt][lkc+5][lrow] = f2tf32(pa1.y);
            As[nxt][lkc+6][lrow] = f2tf32(pa1.z); As[nxt][lkc+7][lrow] = f2tf32(pa1.w);
            Bs[nxt][lkc+0][lrow] = f2tf32(pb0.x); Bs[nxt][lkc+1][lrow] = f2tf32(pb0.y);
            Bs[nxt][lkc+2][lrow] = f2tf32(pb0.z); Bs[nxt][lkc+3][lrow] = f2tf32(pb0.w);
            Bs[nxt][lkc+4][lrow] = f2tf32(pb1.x); Bs[nxt][lkc+5][lrow] = f2tf32(pb1.y);
            Bs[nxt][lkc+6][lrow] = f2tf32(pb1.z); Bs[nxt][lkc+7][lrow] = f2tf32(pb1.w);
        }
        __syncthreads();
        cur ^= 1;
    }

    // epilogue: c0,c1 at (row g, cols 2t,2t+1); c2,c3 at (row g+8)
#pragma unroll
    for (int i = 0; i < 4; i++) {
#pragma unroll
        for (int j = 0; j < 4; j++) {
            size_t r0 = (size_t)(bm + wm + 16 * i + g);
            size_t col = (size_t)(bn + wn + 8 * j + 2 * t);
            float2 v01 = make_float2(acc[i][j][0], acc[i][j][1]);
            float2 v23 = make_float2(acc[i][j][2], acc[i][j][3]);
            *(float2*)&C[r0 * N + col]       = v01;
            *(float2*)&C[(r0 + 8) * N + col] = v23;
        }
    }
}

// ---------------------------------------------------------------------------
// Fused RMSNorm + RoPE, in place. One warp per (token, head) row of 96.
// ---------------------------------------------------------------------------
__global__ void rmsnorm_rope_kernel(float* buf, const float* __restrict__ w,
                                    const int* __restrict__ pos_ids,
                                    int heads, int R)
{
    __shared__ float sh[4][96];
    const int wid  = threadIdx.x >> 5;
    const int lane = threadIdx.x & 31;
    const int row  = blockIdx.x * 4 + wid;
    if (row >= R) return;
    const int token = row / heads;
    float* x = buf + (size_t)row * 96;

    float v0 = x[lane], v1 = x[lane + 32], v2 = x[lane + 64];
    float ss = v0 * v0 + v1 * v1 + v2 * v2;
#pragma unroll
    for (int o = 16; o; o >>= 1) ss += __shfl_xor_sync(0xffffffffu, ss, o);
    float inv = rsqrtf(ss * (1.0f / 96.0f) + 1e-6f);

    sh[wid][lane]      = v0 * inv * w[lane];
    sh[wid][lane + 32] = v1 * inv * w[lane + 32];
    sh[wid][lane + 64] = v2 * inv * w[lane + 64];
    __syncwarp();

    const int pos = pos_ids[token];
    const float* ct = g_cos + pos * 48;
    const float* st = g_sin + pos * 48;
#pragma unroll
    for (int q3 = 0; q3 < 3; q3++) {
        int d = lane + q3 * 32;
        int f = (d < 48) ? d : d - 48;
        float rh = (d < 48) ? -sh[wid][d + 48] : sh[wid][d - 48];
        x[d] = sh[wid][d] * ct[f] + rh * st[f];
    }
}

// ---------------------------------------------------------------------------
// Flash attention (fp32, causal, GQA 4:1). CTA = (q-tile of 32, head, batch),
// 128 threads. Online softmax; causal tiles beyond diagonal skipped.
// ---------------------------------------------------------------------------
__global__ void __launch_bounds__(128) attn_kernel()
{
    const int qt  = blockIdx.x;       // 0..63
    const int h   = blockIdx.y;       // 0..15
    const int b   = blockIdx.z;       // 0..1
    const int kvh = h >> 2;
    const int t   = threadIdx.x;

    __shared__ float Qs[32][97];
    __shared__ float KsT[96][33];
    __shared__ float Vs[32][128];
    __shared__ float Ss[32][33];
    __shared__ float rowm[32], rowl[32], alphas[32];

    const float* qptr = g_q + ((size_t)(b * S_ + qt * 32)) * QN + h * KQD_;
    for (int i = t; i < 32 * 96; i += 128) {
        int r = i / 96, kk = i % 96;
        Qs[r][kk] = qptr[(size_t)r * QN + kk];
    }
    if (t < 32) { rowm[t] = -INFINITY; rowl[t] = 0.f; }

    float O[4][8];
#pragma unroll
    for (int i = 0; i < 4; i++)
#pragma unroll
        for (int j = 0; j < 8; j++) O[i][j] = 0.f;

    const int ra  = t >> 3;
    const int jc0 = (t & 7) * 4;
    const int rg  = t >> 4;
    const int cl  = t & 15;
    const float scale = 1.0f / sqrtf(96.0f);

    for (int kt = 0; kt <= qt; kt++) {
        __syncthreads();
        const float* kptr = g_k + ((size_t)(b * S_ + kt * 32)) * KN + kvh * KQD_;
        for (int i = t; i < 32 * 96; i += 128) {
            int j = i / 96, kk = i % 96;
            KsT[kk][j] = kptr[(size_t)j * KN + kk];
        }
        const float* vptr = g_v + ((size_t)(b * S_ + kt * 32)) * VN + kvh * VD_;
        for (int i = t; i < 32 * 128; i += 128) {
            int j = i >> 7, c = i & 127;
            Vs[j][c] = vptr[(size_t)j * VN + c];
        }
        __syncthreads();

        float a0[4] = {0,0,0,0}, a1[4] = {0,0,0,0};
#pragma unroll 8
        for (int kk = 0; kk < 96; kk++) {
            float q0 = Qs[ra][kk], q1 = Qs[ra + 16][kk];
#pragma unroll
            for (int jj = 0; jj < 4; jj++) {
                float kvv = KsT[kk][jc0 + jj];
                a0[jj] += q0 * kvv;
                a1[jj] += q1 * kvv;
            }
        }
        const bool diag = (kt == qt);
#pragma unroll
        for (int jj = 0; jj < 4; jj++) {
            int j = jc0 + jj;
            float s0 = a0[jj] * scale, s1 = a1[jj] * scale;
            if (diag) {
                if (j > ra)      s0 = -INFINITY;
                if (j > ra + 16) s1 = -INFINITY;
            }
            Ss[ra][j]      = s0;
            Ss[ra + 16][j] = s1;
        }
        __syncthreads();

        {
            int row = t >> 2, sub = t & 3;
            float pv[8], mloc = -INFINITY;
#pragma unroll
            for (int i2 = 0; i2 < 8; i2++) {
                pv[i2] = Ss[row][sub * 8 + i2];
                mloc = fmaxf(mloc, pv[i2]);
            }
            mloc = fmaxf(mloc, __shfl_xor_sync(0xffffffffu, mloc, 1));
            mloc = fmaxf(mloc, __shfl_xor_sync(0xffffffffu, mloc, 2));
            float mold = rowm[row];
            float mnew = fmaxf(mold, mloc);
            float sum = 0.f;
#pragma unroll
            for (int i2 = 0; i2 < 8; i2++) {
                float p = __expf(pv[i2] - mnew);
                sum += p;
                Ss[row][sub * 8 + i2] = p;
            }
            sum += __shfl_xor_sync(0xffffffffu, sum, 1);
            sum += __shfl_xor_sync(0xffffffffu, sum, 2);
            if (sub == 0) {
                float alpha = __expf(mold - mnew);
                rowm[row]   = mnew;
                rowl[row]   = rowl[row] * alpha + sum;
                alphas[row] = alpha;
            }
        }
        __syncthreads();

#pragma unroll
        for (int ri = 0; ri < 4; ri++) {
            float a = alphas[rg + 8 * ri];
#pragma unroll
            for (int ci = 0; ci < 8; ci++) O[ri][ci] *= a;
        }
#pragma unroll 4
        for (int j = 0; j < 32; j++) {
            float p0 = Ss[rg][j], p1 = Ss[rg + 8][j];
            float p2 = Ss[rg + 16][j], p3 = Ss[rg + 24][j];
#pragma unroll
            for (int ci = 0; ci < 8; ci++) {
                float v = Vs[j][cl + (ci << 4)];
                O[0][ci] += p0 * v;
                O[1][ci] += p1 * v;
                O[2][ci] += p2 * v;
                O[3][ci] += p3 * v;
            }
        }
    }

    float* optr = g_ao + ((size_t)(b * S_ + qt * 32)) * ON + h * VD_;
#pragma unroll
    for (int ri = 0; ri < 4; ri++) {
        int r = rg + 8 * ri;
        float invl = 1.0f / rowl[r];
#pragma unroll
        for (int ci = 0; ci < 8; ci++)
            optr[(size_t)r * ON + cl + (ci << 4)] = O[ri][ci] * invl;
    }
}

// ---------------------------------------------------------------------------
extern "C" void kernel_launch(void* const* d_in, const int* in_sizes, int n_in,
                              void* d_out, int out_size)
{
    const float* hidden = (const float*)d_in[0];
    const int*   pos    = (const int*)  d_in[1];
    const float* Wq     = (const float*)d_in[2];
    const float* Wk     = (const float*)d_in[3];
    const float* Wv     = (const float*)d_in[4];
    const float* Wo     = (const float*)d_in[5];
    const float* qw     = (const float*)d_in[6];
    const float* kw     = (const float*)d_in[7];
    float* out = (float*)d_out;

    void *pq, *pk, *pv, *pa;
    cudaGetSymbolAddress(&pq, g_q);
    cudaGetSymbolAddress(&pk, g_k);
    cudaGetSymbolAddress(&pv, g_v);
    cudaGetSymbolAddress(&pa, g_ao);
    float* qb = (float*)pq;
    float* kb = (float*)pk;
    float* vb = (float*)pv;
    float* ab = (float*)pa;

    // 1. RoPE table
    rope_table_kernel<<<(S_ * 48 + 255) / 256, 256>>>();

    // 2. QKV projections (tf32 tensor cores)
    sgemm_tf32<<<dim3(QN / 128, TOK / 128), 256>>>(hidden, Wq, qb, TOK, QN, D_);
    sgemm_tf32<<<dim3(KN / 128, TOK / 128), 256>>>(hidden, Wk, kb, TOK, KN, D_);
    sgemm_tf32<<<dim3(VN / 128, TOK / 128), 256>>>(hidden, Wv, vb, TOK, VN, D_);

    // 3. RMSNorm + RoPE (in place)
    rmsnorm_rope_kernel<<<(TOK * H_) / 4, 128>>>(qb, qw, pos, H_, TOK * H_);
    rmsnorm_rope_kernel<<<(TOK * KV_) / 4, 128>>>(kb, kw, pos, KV_, TOK * KV_);

    // 4. Attention
    attn_kernel<<<dim3(S_ / 32, H_, B_), 128>>>();

    // 5. Output projection (tf32 tensor cores)
    sgemm_tf32<<<dim3(D_ / 128, TOK / 128), 256>>>(ab, Wo, out, TOK, D_, ON);
}

// round 3
// speedup vs baseline: 2.7148x; 1.7032x over previous
#include <cuda_runtime.h>
#include <math.h>

// Problem constants
#define B_   2
#define S_   2048
#define D_   2048
#define H_   16
#define KV_  4
#define KQD_ 96
#define VD_  128
#define TOK  (B_*S_)       // 4096 tokens
#define QN   (H_*KQD_)     // 1536
#define KN   (KV_*KQD_)    // 384
#define VN   (KV_*VD_)     // 512
#define ON   (H_*VD_)      // 2048

// Scratch (device globals; allocation APIs are forbidden)
__device__ float g_q [TOK * QN];
__device__ float g_k [TOK * KN];
__device__ float g_v [TOK * VN];
__device__ float g_ao[TOK * ON];
__device__ float g_cos[S_ * 48];
__device__ float g_sin[S_ * 48];

// ---------------------------------------------------------------------------
__global__ void rope_table_kernel() {
    int i = blockIdx.x * blockDim.x + threadIdx.x;
    if (i >= S_ * 48) return;
    int pos = i / 48, j = i % 48;
    double inv = exp(-log(10000.0) * (double)j / 48.0);
    double ang = (double)pos * inv;
    g_cos[i] = (float)cos(ang);
    g_sin[i] = (float)sin(ang);
}

// ---------------------------------------------------------------------------
// TF32 helpers
// ---------------------------------------------------------------------------
__device__ __forceinline__ unsigned f2tf32(float x) {
    unsigned r;
    asm("cvt.rna.tf32.f32 %0, %1;" : "=r"(r) : "f"(x));
    return r;
}
__device__ __forceinline__ void mma_tf32(float* c, const unsigned* a, const unsigned* b) {
    asm volatile(
        "mma.sync.aligned.m16n8k8.row.col.f32.tf32.tf32.f32 "
        "{%0,%1,%2,%3}, {%4,%5,%6,%7}, {%8,%9}, {%0,%1,%2,%3};\n"
        : "+f"(c[0]), "+f"(c[1]), "+f"(c[2]), "+f"(c[3])
        : "r"(a[0]), "r"(a[1]), "r"(a[2]), "r"(a[3]),
          "r"(b[0]), "r"(b[1]));
}

// ---------------------------------------------------------------------------
// TF32 tensor-core GEMM-NT (from R2, validated)
// ---------------------------------------------------------------------------
#define BKT 16
#define SSTR 136

__global__ void __launch_bounds__(256) sgemm_tf32(
    const float* __restrict__ A, const float* __restrict__ Bm,
    float* __restrict__ C, int M, int N, int K)
{
    __shared__ unsigned As[2][BKT][SSTR];
    __shared__ unsigned Bs[2][BKT][SSTR];

    const int tid  = threadIdx.x;
    const int bm   = blockIdx.y << 7;
    const int bn   = blockIdx.x << 7;
    const int warp = tid >> 5;
    const int lane = tid & 31;
    const int g    = lane >> 2;
    const int t    = lane & 3;
    const int wm   = (warp >> 2) * 64;
    const int wn   = (warp & 3) * 32;

    const int lrow = tid >> 1;
    const int lkc  = (tid & 1) * 8;
    const float* Ap = A  + (size_t)(bm + lrow) * K + lkc;
    const float* Bp = Bm + (size_t)(bn + lrow) * K + lkc;

    float acc[4][4][4];
#pragma unroll
    for (int i = 0; i < 4; i++)
#pragma unroll
        for (int j = 0; j < 4; j++)
#pragma unroll
            for (int r = 0; r < 4; r++) acc[i][j][r] = 0.f;

    float4 pa0 = *(const float4*)(Ap + 0);
    float4 pa1 = *(const float4*)(Ap + 4);
    float4 pb0 = *(const float4*)(Bp + 0);
    float4 pb1 = *(const float4*)(Bp + 4);
    {
        As[0][lkc+0][lrow] = f2tf32(pa0.x); As[0][lkc+1][lrow] = f2tf32(pa0.y);
        As[0][lkc+2][lrow] = f2tf32(pa0.z); As[0][lkc+3][lrow] = f2tf32(pa0.w);
        As[0][lkc+4][lrow] = f2tf32(pa1.x); As[0][lkc+5][lrow] = f2tf32(pa1.y);
        As[0][lkc+6][lrow] = f2tf32(pa1.z); As[0][lkc+7][lrow] = f2tf32(pa1.w);
        Bs[0][lkc+0][lrow] = f2tf32(pb0.x); Bs[0][lkc+1][lrow] = f2tf32(pb0.y);
        Bs[0][lkc+2][lrow] = f2tf32(pb0.z); Bs[0][lkc+3][lrow] = f2tf32(pb0.w);
        Bs[0][lkc+4][lrow] = f2tf32(pb1.x); Bs[0][lkc+5][lrow] = f2tf32(pb1.y);
        Bs[0][lkc+6][lrow] = f2tf32(pb1.z); Bs[0][lkc+7][lrow] = f2tf32(pb1.w);
    }
    __syncthreads();

    int cur = 0;
    for (int k0 = BKT; k0 <= K; k0 += BKT) {
        const bool more = (k0 < K);
        if (more) {
            pa0 = *(const float4*)(Ap + k0);
            pa1 = *(const float4*)(Ap + k0 + 4);
            pb0 = *(const float4*)(Bp + k0);
            pb1 = *(const float4*)(Bp + k0 + 4);
        }
#pragma unroll
        for (int kh = 0; kh < 2; kh++) {
            const int k8 = kh * 8;
            unsigned af[4][4], bf[4][2];
#pragma unroll
            for (int i = 0; i < 4; i++) {
                int m = wm + 16 * i;
                af[i][0] = As[cur][k8 + t    ][m + g];
                af[i][1] = As[cur][k8 + t    ][m + g + 8];
                af[i][2] = As[cur][k8 + t + 4][m + g];
                af[i][3] = As[cur][k8 + t + 4][m + g + 8];
            }
#pragma unroll
            for (int j = 0; j < 4; j++) {
                int n = wn + 8 * j;
                bf[j][0] = Bs[cur][k8 + t    ][n + g];
                bf[j][1] = Bs[cur][k8 + t + 4][n + g];
            }
#pragma unroll
            for (int i = 0; i < 4; i++)
#pragma unroll
                for (int j = 0; j < 4; j++)
                    mma_tf32(acc[i][j], af[i], bf[j]);
        }
        if (more) {
            int nxt = cur ^ 1;
            As[nxt][lkc+0][lrow] = f2tf32(pa0.x); As[nxt][lkc+1][lrow] = f2tf32(pa0.y);
            As[nxt][lkc+2][lrow] = f2tf32(pa0.z); As[nxt][lkc+3][lrow] = f2tf32(pa0.w);
            As[nxt][lkc+4][lrow] = f2tf32(pa1.x); As[nxt][lkc+5][lrow] = f2tf32(pa1.y);
            As[nxt][lkc+6][lrow] = f2tf32(pa1.z); As[nxt][lkc+7][lrow] = f2tf32(pa1.w);
            Bs[nxt][lkc+0][lrow] = f2tf32(pb0.x); Bs[nxt][lkc+1][lrow] = f2tf32(pb0.y);
            Bs[nxt][lkc+2][lrow] = f2tf32(pb0.z); Bs[nxt][lkc+3][lrow] = f2tf32(pb0.w);
            Bs[nxt][lkc+4][lrow] = f2tf32(pb1.x); Bs[nxt][lkc+5][lrow] = f2tf32(pb1.y);
            Bs[nxt][lkc+6][lrow] = f2tf32(pb1.z); Bs[nxt][lkc+7][lrow] = f2tf32(pb1.w);
        }
        __syncthreads();
        cur ^= 1;
    }

#pragma unroll
    for (int i = 0; i < 4; i++) {
#pragma unroll
        for (int j = 0; j < 4; j++) {
            size_t r0 = (size_t)(bm + wm + 16 * i + g);
            size_t col = (size_t)(bn + wn + 8 * j + 2 * t);
            float2 v01 = make_float2(acc[i][j][0], acc[i][j][1]);
            float2 v23 = make_float2(acc[i][j][2], acc[i][j][3]);
            *(float2*)&C[r0 * N + col]       = v01;
            *(float2*)&C[(r0 + 8) * N + col] = v23;
        }
    }
}

// ---------------------------------------------------------------------------
// Fused RMSNorm + RoPE, in place. One warp per (token, head) row of 96.
// ---------------------------------------------------------------------------
__global__ void rmsnorm_rope_kernel(float* buf, const float* __restrict__ w,
                                    const int* __restrict__ pos_ids,
                                    int heads, int R)
{
    __shared__ float sh[4][96];
    const int wid  = threadIdx.x >> 5;
    const int lane = threadIdx.x & 31;
    const int row  = blockIdx.x * 4 + wid;
    if (row >= R) return;
    const int token = row / heads;
    float* x = buf + (size_t)row * 96;

    float v0 = x[lane], v1 = x[lane + 32], v2 = x[lane + 64];
    float ss = v0 * v0 + v1 * v1 + v2 * v2;
#pragma unroll
    for (int o = 16; o; o >>= 1) ss += __shfl_xor_sync(0xffffffffu, ss, o);
    float inv = rsqrtf(ss * (1.0f / 96.0f) + 1e-6f);

    sh[wid][lane]      = v0 * inv * w[lane];
    sh[wid][lane + 32] = v1 * inv * w[lane + 32];
    sh[wid][lane + 64] = v2 * inv * w[lane + 64];
    __syncwarp();

    const int pos = pos_ids[token];
    const float* ct = g_cos + pos * 48;
    const float* st = g_sin + pos * 48;
#pragma unroll
    for (int q3 = 0; q3 < 3; q3++) {
        int d = lane + q3 * 32;
        int f = (d < 48) ? d : d - 48;
        float rh = (d < 48) ? -sh[wid][d + 48] : sh[wid][d - 48];
        x[d] = sh[wid][d] * ct[f] + rh * st[f];
    }
}

// ---------------------------------------------------------------------------
// Tensor-core flash attention (tf32 MMA, causal, GQA 4:1).
// CTA = (64-query tile, head, batch), 128 threads / 4 warps.
// Warp w owns query rows [w*16, w*16+16): S stripe, softmax stats, O stripe.
// Smem (dynamic 86KB): Qs[64][100], Ks[64][100] (union Ps[4][16][68]), Vs[64][136]
// All fragment LDS patterns conflict-free by stride choice (mod-32 = 4 / 8 / 4).
// ---------------------------------------------------------------------------
#define QT64 64
#define QSTR 100   // 100 % 32 == 4
#define VSTR 136   // 136 % 32 == 8
#define PSTR 68    //  68 % 32 == 4
#define ATTN_SMEM_U (64*QSTR + 64*QSTR + 64*VSTR)   // 21504 words = 86016 B

extern __shared__ unsigned ds_attn[];

__global__ void __launch_bounds__(128) attn_tc_kernel()
{
    const int qt  = blockIdx.x;       // 0..31
    const int h   = blockIdx.y;
    const int b   = blockIdx.z;
    const int kvh = h >> 2;
    const int tid = threadIdx.x;
    const int w   = tid >> 5;
    const int lane = tid & 31;
    const int g   = lane >> 2;
    const int t   = lane & 3;
    const int wm  = w * 16;

    unsigned* Qs = ds_attn;                  // [64][QSTR]
    unsigned* Ks = ds_attn + 64 * QSTR;      // [64][QSTR]
    unsigned* Psw = Ks + wm * PSTR;          // this warp's P: [16][PSTR]
    unsigned* Vs = ds_attn + 2 * 64 * QSTR;  // [64][VSTR]

    const float scale = 1.0f / sqrtf(96.0f);

    // Load Q tile (once), scale folded, tf32, row-major stride QSTR
    const float* qbase = g_q + ((size_t)(b * S_ + qt * QT64)) * QN + h * KQD_;
    for (int it = tid; it < 64 * 24; it += 128) {
        int r = it / 24, c4 = (it % 24) * 4;
        float4 v = *(const float4*)(qbase + (size_t)r * QN + c4);
        uint4 u = make_uint4(f2tf32(v.x * scale), f2tf32(v.y * scale),
                             f2tf32(v.z * scale), f2tf32(v.w * scale));
        *(uint4*)&Qs[r * QSTR + c4] = u;
    }

    float o[16][4];
#pragma unroll
    for (int j = 0; j < 16; j++)
#pragma unroll
        for (int r = 0; r < 4; r++) o[j][r] = 0.f;
    float m0 = -INFINITY, m1 = -INFINITY, l0 = 0.f, l1 = 0.f;

    const int row0g = qt * QT64 + wm + g;     // global q row for c0,c1
    const int row1g = row0g + 8;              // for c2,c3

    for (int kt = 0; kt <= qt; kt++) {
        __syncthreads();   // prev PV done everywhere; Ks/Vs free

        // Load K tile: [64 keys][96] -> Ks row-major stride QSTR (tf32)
        const float* kbase = g_k + ((size_t)(b * S_ + kt * QT64)) * KN + kvh * KQD_;
        for (int it = tid; it < 64 * 24; it += 128) {
            int r = it / 24, c4 = (it % 24) * 4;
            float4 v = *(const float4*)(kbase + (size_t)r * KN + c4);
            uint4 u = make_uint4(f2tf32(v.x), f2tf32(v.y), f2tf32(v.z), f2tf32(v.w));
            *(uint4*)&Ks[r * QSTR + c4] = u;
        }
        // Load V tile: [64 keys][128] -> Vs stride VSTR (tf32)
        const float* vbase = g_v + ((size_t)(b * S_ + kt * QT64)) * VN + kvh * VD_;
        for (int it = tid; it < 64 * 32; it += 128) {
            int r = it / 32, c4 = (it % 32) * 4;
            float4 v = *(const float4*)(vbase + (size_t)r * VN + c4);
            uint4 u = make_uint4(f2tf32(v.x), f2tf32(v.y), f2tf32(v.z), f2tf32(v.w));
            *(uint4*)&Vs[r * VSTR + c4] = u;
        }
        __syncthreads();

        // S = Q K^T  : 16x64 per warp, K-dim 96
        float s[8][4];
#pragma unroll
        for (int j = 0; j < 8; j++)
#pragma unroll
            for (int r = 0; r < 4; r++) s[j][r] = 0.f;
#pragma unroll
        for (int k8 = 0; k8 < 96; k8 += 8) {
            unsigned af[4];
            af[0] = Qs[(wm + g    ) * QSTR + k8 + t    ];
            af[1] = Qs[(wm + g + 8) * QSTR + k8 + t    ];
            af[2] = Qs[(wm + g    ) * QSTR + k8 + t + 4];
            af[3] = Qs[(wm + g + 8) * QSTR + k8 + t + 4];
#pragma unroll
            for (int j = 0; j < 8; j++) {
                unsigned bf[2];
                bf[0] = Ks[(8 * j + g) * QSTR + k8 + t    ];
                bf[1] = Ks[(8 * j + g) * QSTR + k8 + t + 4];
                mma_tf32(s[j], af, bf);
            }
        }

        // Causal mask on diagonal tile
        if (kt == qt) {
#pragma unroll
            for (int j = 0; j < 8; j++) {
                int c0 = kt * QT64 + 8 * j + 2 * t;
                if (c0     > row0g) s[j][0] = -INFINITY;
                if (c0 + 1 > row0g) s[j][1] = -INFINITY;
                if (c0     > row1g) s[j][2] = -INFINITY;
                if (c0 + 1 > row1g) s[j][3] = -INFINITY;
            }
        }

        // Online softmax (rows g, g+8 owned by quad lanes t=0..3)
        float ml0 = -INFINITY, ml1 = -INFINITY;
#pragma unroll
        for (int j = 0; j < 8; j++) {
            ml0 = fmaxf(ml0, fmaxf(s[j][0], s[j][1]));
            ml1 = fmaxf(ml1, fmaxf(s[j][2], s[j][3]));
        }
        ml0 = fmaxf(ml0, __shfl_xor_sync(0xffffffffu, ml0, 1));
        ml0 = fmaxf(ml0, __shfl_xor_sync(0xffffffffu, ml0, 2));
        ml1 = fmaxf(ml1, __shfl_xor_sync(0xffffffffu, ml1, 1));
        ml1 = fmaxf(ml1, __shfl_xor_sync(0xffffffffu, ml1, 2));
        float mn0 = fmaxf(m0, ml0), mn1 = fmaxf(m1, ml1);
        float al0 = __expf(m0 - mn0), al1 = __expf(m1 - mn1);
        m0 = mn0; m1 = mn1;
        float sum0 = 0.f, sum1 = 0.f;
#pragma unroll
        for (int j = 0; j < 8; j++) {
            s[j][0] = __expf(s[j][0] - mn0); sum0 += s[j][0];
            s[j][1] = __expf(s[j][1] - mn0); sum0 += s[j][1];
            s[j][2] = __expf(s[j][2] - mn1); sum1 += s[j][2];
            s[j][3] = __expf(s[j][3] - mn1); sum1 += s[j][3];
        }
        sum0 += __shfl_xor_sync(0xffffffffu, sum0, 1);
        sum0 += __shfl_xor_sync(0xffffffffu, sum0, 2);
        sum1 += __shfl_xor_sync(0xffffffffu, sum1, 1);
        sum1 += __shfl_xor_sync(0xffffffffu, sum1, 2);
        l0 = l0 * al0 + sum0;
        l1 = l1 * al1 + sum1;
#pragma unroll
        for (int j = 0; j < 16; j++) {
            o[j][0] *= al0; o[j][1] *= al0;
            o[j][2] *= al1; o[j][3] *= al1;
        }

        __syncthreads();   // all warps done reading Ks -> Ps region writable

        // Store P (tf32) into per-warp Ps [16 rows][PSTR], k-minor
#pragma unroll
        for (int j = 0; j < 8; j++) {
            *(uint2*)&Psw[g * PSTR + 8 * j + 2 * t] =
                make_uint2(f2tf32(s[j][0]), f2tf32(s[j][1]));
            *(uint2*)&Psw[(g + 8) * PSTR + 8 * j + 2 * t] =
                make_uint2(f2tf32(s[j][2]), f2tf32(s[j][3]));
        }
        __syncwarp();

        // O += P V : 16x128 per warp, K-dim 64
#pragma unroll
        for (int k8 = 0; k8 < 64; k8 += 8) {
            unsigned af[4];
            af[0] = Psw[(g    ) * PSTR + k8 + t    ];
            af[1] = Psw[(g + 8) * PSTR + k8 + t    ];
            af[2] = Psw[(g    ) * PSTR + k8 + t + 4];
            af[3] = Psw[(g + 8) * PSTR + k8 + t + 4];
#pragma unroll
            for (int jn = 0; jn < 16; jn++) {
                unsigned bf[2];
                bf[0] = Vs[(k8 + t    ) * VSTR + 8 * jn + g];
                bf[1] = Vs[(k8 + t + 4) * VSTR + 8 * jn + g];
                mma_tf32(o[jn], af, bf);
            }
        }
    }

    // Epilogue
    float inv0 = 1.0f / l0, inv1 = 1.0f / l1;
    float* ob = g_ao + ((size_t)(b * S_)) * ON + h * VD_;
    size_t r0 = (size_t)(qt * QT64 + wm + g);
    size_t r1 = r0 + 8;
#pragma unroll
    for (int jn = 0; jn < 16; jn++) {
        int col = 8 * jn + 2 * t;
        *(float2*)&ob[r0 * ON + col] = make_float2(o[jn][0] * inv0, o[jn][1] * inv0);
        *(float2*)&ob[r1 * ON + col] = make_float2(o[jn][2] * inv1, o[jn][3] * inv1);
    }
}

// ---------------------------------------------------------------------------
extern "C" void kernel_launch(void* const* d_in, const int* in_sizes, int n_in,
                              void* d_out, int out_size)
{
    const float* hidden = (const float*)d_in[0];
    const int*   pos    = (const int*)  d_in[1];
    const float* Wq     = (const float*)d_in[2];
    const float* Wk     = (const float*)d_in[3];
    const float* Wv     = (const float*)d_in[4];
    const float* Wo     = (const float*)d_in[5];
    const float* qw     = (const float*)d_in[6];
    const float* kw     = (const float*)d_in[7];
    float* out = (float*)d_out;

    void *pq, *pk, *pv, *pa;
    cudaGetSymbolAddress(&pq, g_q);
    cudaGetSymbolAddress(&pk, g_k);
    cudaGetSymbolAddress(&pv, g_v);
    cudaGetSymbolAddress(&pa, g_ao);
    float* qb = (float*)pq;
    float* kb = (float*)pk;
    float* vb = (float*)pv;
    float* ab = (float*)pa;

    static int smem_set = 0;
    if (!smem_set) {
        cudaFuncSetAttribute(attn_tc_kernel,
                             cudaFuncAttributeMaxDynamicSharedMemorySize,
                             ATTN_SMEM_U * 4);
        smem_set = 1;
    }

    // 1. RoPE table
    rope_table_kernel<<<(S_ * 48 + 255) / 256, 256>>>();

    // 2. QKV projections (tf32 tensor cores)
    sgemm_tf32<<<dim3(QN / 128, TOK / 128), 256>>>(hidden, Wq, qb, TOK, QN, D_);
    sgemm_tf32<<<dim3(KN / 128, TOK / 128), 256>>>(hidden, Wk, kb, TOK, KN, D_);
    sgemm_tf32<<<dim3(VN / 128, TOK / 128), 256>>>(hidden, Wv, vb, TOK, VN, D_);

    // 3. RMSNorm + RoPE (in place)
    rmsnorm_rope_kernel<<<(TOK * H_) / 4, 128>>>(qb, qw, pos, H_, TOK * H_);
    rmsnorm_rope_kernel<<<(TOK * KV_) / 4, 128>>>(kb, kw, pos, KV_, TOK * KV_);

    // 4. Tensor-core flash attention
    attn_tc_kernel<<<dim3(S_ / QT64, H_, B_), 128, ATTN_SMEM_U * 4>>>();

    // 5. Output projection (tf32 tensor cores)
    sgemm_tf32<<<dim3(D_ / 128, TOK / 128), 256>>>(ab, Wo, out, TOK, D_, ON);
}

// round 4
// speedup vs baseline: 3.0833x; 1.1358x over previous
#include <cuda_runtime.h>
#include <math.h>

// Problem constants
#define B_   2
#define S_   2048
#define D_   2048
#define H_   16
#define KV_  4
#define KQD_ 96
#define VD_  128
#define TOK  (B_*S_)       // 4096
#define QN   (H_*KQD_)     // 1536
#define KN   (KV_*KQD_)    // 384
#define VN   (KV_*VD_)     // 512
#define ON   (H_*VD_)      // 2048

__device__ float g_q [TOK * QN];
__device__ float g_k [TOK * KN];
__device__ float g_v [TOK * VN];
__device__ float g_ao[TOK * ON];
__device__ float g_cos[S_ * 48];
__device__ float g_sin[S_ * 48];

// ---------------------------------------------------------------------------
__global__ void rope_table_kernel() {
    int i = blockIdx.x * blockDim.x + threadIdx.x;
    if (i >= S_ * 48) return;
    int pos = i / 48, j = i % 48;
    double inv = exp(-log(10000.0) * (double)j / 48.0);
    double ang = (double)pos * inv;
    g_cos[i] = (float)cos(ang);
    g_sin[i] = (float)sin(ang);
}

// ---------------------------------------------------------------------------
__device__ __forceinline__ unsigned f2tf32(float x) {
    unsigned r;
    asm("cvt.rna.tf32.f32 %0, %1;" : "=r"(r) : "f"(x));
    return r;
}
__device__ __forceinline__ void mma_tf32(float* c, const unsigned* a, const unsigned* b) {
    asm volatile(
        "mma.sync.aligned.m16n8k8.row.col.f32.tf32.tf32.f32 "
        "{%0,%1,%2,%3}, {%4,%5,%6,%7}, {%8,%9}, {%0,%1,%2,%3};\n"
        : "+f"(c[0]), "+f"(c[1]), "+f"(c[2]), "+f"(c[3])
        : "r"(a[0]), "r"(a[1]), "r"(a[2]), "r"(a[3]),
          "r"(b[0]), "r"(b[1]));
}
__device__ __forceinline__ void cp_async16(unsigned saddr, const void* g) {
    asm volatile("cp.async.cg.shared.global [%0], [%1], 16;\n" :: "r"(saddr), "l"(g));
}
#define CP_COMMIT() asm volatile("cp.async.commit_group;\n" ::: "memory")
#define CP_WAIT1()  asm volatile("cp.async.wait_group 1;\n" ::: "memory")

// ---------------------------------------------------------------------------
// TF32 GEMM-NT core (128x128 tile, BK=16, double-buffered). RND: round output
// to tf32 bits (for V, consumed as tf32 by attention).
// ---------------------------------------------------------------------------
#define BKT 16
#define SSTR 136

template<bool RND>
__device__ __forceinline__ void gemm_body(
    const float* __restrict__ A, const float* __restrict__ Bm,
    float* __restrict__ C, int N, int K, int bm, int bn,
    unsigned (*As)[BKT][SSTR], unsigned (*Bs)[BKT][SSTR])
{
    const int tid  = threadIdx.x;
    const int warp = tid >> 5;
    const int lane = tid & 31;
    const int g    = lane >> 2;
    const int t    = lane & 3;
    const int wm   = (warp >> 2) * 64;
    const int wn   = (warp & 3) * 32;

    const int lrow = tid >> 1;
    const int lkc  = (tid & 1) * 8;
    const float* Ap = A  + (size_t)(bm + lrow) * K + lkc;
    const float* Bp = Bm + (size_t)(bn + lrow) * K + lkc;

    float acc[4][4][4];
#pragma unroll
    for (int i = 0; i < 4; i++)
#pragma unroll
        for (int j = 0; j < 4; j++)
#pragma unroll
            for (int r = 0; r < 4; r++) acc[i][j][r] = 0.f;

    float4 pa0 = *(const float4*)(Ap + 0);
    float4 pa1 = *(const float4*)(Ap + 4);
    float4 pb0 = *(const float4*)(Bp + 0);
    float4 pb1 = *(const float4*)(Bp + 4);
    {
        As[0][lkc+0][lrow] = f2tf32(pa0.x); As[0][lkc+1][lrow] = f2tf32(pa0.y);
        As[0][lkc+2][lrow] = f2tf32(pa0.z); As[0][lkc+3][lrow] = f2tf32(pa0.w);
        As[0][lkc+4][lrow] = f2tf32(pa1.x); As[0][lkc+5][lrow] = f2tf32(pa1.y);
        As[0][lkc+6][lrow] = f2tf32(pa1.z); As[0][lkc+7][lrow] = f2tf32(pa1.w);
        Bs[0][lkc+0][lrow] = f2tf32(pb0.x); Bs[0][lkc+1][lrow] = f2tf32(pb0.y);
        Bs[0][lkc+2][lrow] = f2tf32(pb0.z); Bs[0][lkc+3][lrow] = f2tf32(pb0.w);
        Bs[0][lkc+4][lrow] = f2tf32(pb1.x); Bs[0][lkc+5][lrow] = f2tf32(pb1.y);
        Bs[0][lkc+6][lrow] = f2tf32(pb1.z); Bs[0][lkc+7][lrow] = f2tf32(pb1.w);
    }
    __syncthreads();

    int cur = 0;
    for (int k0 = BKT; k0 <= K; k0 += BKT) {
        const bool more = (k0 < K);
        if (more) {
            pa0 = *(const float4*)(Ap + k0);
            pa1 = *(const float4*)(Ap + k0 + 4);
            pb0 = *(const float4*)(Bp + k0);
            pb1 = *(const float4*)(Bp + k0 + 4);
        }
#pragma unroll
        for (int kh = 0; kh < 2; kh++) {
            const int k8 = kh * 8;
            unsigned af[4][4], bf[4][2];
#pragma unroll
            for (int i = 0; i < 4; i++) {
                int m = wm + 16 * i;
                af[i][0] = As[cur][k8 + t    ][m + g];
                af[i][1] = As[cur][k8 + t    ][m + g + 8];
                af[i][2] = As[cur][k8 + t + 4][m + g];
                af[i][3] = As[cur][k8 + t + 4][m + g + 8];
            }
#pragma unroll
            for (int j = 0; j < 4; j++) {
                int n = wn + 8 * j;
                bf[j][0] = Bs[cur][k8 + t    ][n + g];
                bf[j][1] = Bs[cur][k8 + t + 4][n + g];
            }
#pragma unroll
            for (int i = 0; i < 4; i++)
#pragma unroll
                for (int j = 0; j < 4; j++)
                    mma_tf32(acc[i][j], af[i], bf[j]);
        }
        if (more) {
            int nxt = cur ^ 1;
            As[nxt][lkc+0][lrow] = f2tf32(pa0.x); As[nxt][lkc+1][lrow] = f2tf32(pa0.y);
            As[nxt][lkc+2][lrow] = f2tf32(pa0.z); As[nxt][lkc+3][lrow] = f2tf32(pa0.w);
            As[nxt][lkc+4][lrow] = f2tf32(pa1.x); As[nxt][lkc+5][lrow] = f2tf32(pa1.y);
            As[nxt][lkc+6][lrow] = f2tf32(pa1.z); As[nxt][lkc+7][lrow] = f2tf32(pa1.w);
            Bs[nxt][lkc+0][lrow] = f2tf32(pb0.x); Bs[nxt][lkc+1][lrow] = f2tf32(pb0.y);
            Bs[nxt][lkc+2][lrow] = f2tf32(pb0.z); Bs[nxt][lkc+3][lrow] = f2tf32(pb0.w);
            Bs[nxt][lkc+4][lrow] = f2tf32(pb1.x); Bs[nxt][lkc+5][lrow] = f2tf32(pb1.y);
            Bs[nxt][lkc+6][lrow] = f2tf32(pb1.z); Bs[nxt][lkc+7][lrow] = f2tf32(pb1.w);
        }
        __syncthreads();
        cur ^= 1;
    }

#pragma unroll
    for (int i = 0; i < 4; i++) {
#pragma unroll
        for (int j = 0; j < 4; j++) {
            size_t r0 = (size_t)(bm + wm + 16 * i + g);
            size_t col = (size_t)(bn + wn + 8 * j + 2 * t);
            float v0 = acc[i][j][0], v1 = acc[i][j][1];
            float v2 = acc[i][j][2], v3 = acc[i][j][3];
            if (RND) {
                v0 = __uint_as_float(f2tf32(v0)); v1 = __uint_as_float(f2tf32(v1));
                v2 = __uint_as_float(f2tf32(v2)); v3 = __uint_as_float(f2tf32(v3));
            }
            *(float2*)&C[r0 * N + col]       = make_float2(v0, v1);
            *(float2*)&C[(r0 + 8) * N + col] = make_float2(v2, v3);
        }
    }
}

// O projection (plain)
__global__ void __launch_bounds__(256) sgemm_tf32(
    const float* __restrict__ A, const float* __restrict__ Bm,
    float* __restrict__ C, int M, int N, int K)
{
    __shared__ unsigned As[2][BKT][SSTR];
    __shared__ unsigned Bs[2][BKT][SSTR];
    gemm_body<false>(A, Bm, C, N, K, blockIdx.y << 7, blockIdx.x << 7, As, Bs);
}

// Fused QKV projection: z=0 Q(12 blk), z=1 K(3 blk), z=2 V(4 blk, rounded)
__global__ void __launch_bounds__(256) sgemm_qkv(
    const float* __restrict__ A,
    const float* __restrict__ Wq, const float* __restrict__ Wk,
    const float* __restrict__ Wv,
    float* __restrict__ qb, float* __restrict__ kb, float* __restrict__ vb)
{
    __shared__ unsigned As[2][BKT][SSTR];
    __shared__ unsigned Bs[2][BKT][SSTR];
    const int z = blockIdx.z, bx = blockIdx.x;
    const int bm = blockIdx.y << 7, bn = bx << 7;
    if (z == 0) {
        gemm_body<false>(A, Wq, qb, QN, D_, bm, bn, As, Bs);
    } else if (z == 1) {
        if (bx >= KN / 128) return;
        gemm_body<false>(A, Wk, kb, KN, D_, bm, bn, As, Bs);
    } else {
        if (bx >= VN / 128) return;
        gemm_body<true>(A, Wv, vb, VN, D_, bm, bn, As, Bs);
    }
}

// ---------------------------------------------------------------------------
// Fused RMSNorm+RoPE over Q rows then K rows. K output rounded to tf32 bits.
// ---------------------------------------------------------------------------
#define QROWS (TOK * H_)
#define KROWS (TOK * KV_)

__global__ void rmsnorm_rope_fused(float* qb, float* kb,
                                   const float* __restrict__ qw,
                                   const float* __restrict__ kw,
                                   const int* __restrict__ pos_ids)
{
    __shared__ float sh[4][96];
    const int wid  = threadIdx.x >> 5;
    const int lane = threadIdx.x & 31;
    const int row  = blockIdx.x * 4 + wid;
    if (row >= QROWS + KROWS) return;

    const bool isK = (row >= QROWS);
    const int  r   = isK ? row - QROWS : row;
    const int  token = isK ? (r / KV_) : (r / H_);
    float* x = (isK ? kb : qb) + (size_t)r * 96;
    const float* w = isK ? kw : qw;

    float v0 = x[lane], v1 = x[lane + 32], v2 = x[lane + 64];
    float ss = v0 * v0 + v1 * v1 + v2 * v2;
#pragma unroll
    for (int o = 16; o; o >>= 1) ss += __shfl_xor_sync(0xffffffffu, ss, o);
    float inv = rsqrtf(ss * (1.0f / 96.0f) + 1e-6f);

    sh[wid][lane]      = v0 * inv * w[lane];
    sh[wid][lane + 32] = v1 * inv * w[lane + 32];
    sh[wid][lane + 64] = v2 * inv * w[lane + 64];
    __syncwarp();

    const int pos = pos_ids[token];
    const float* ct = g_cos + pos * 48;
    const float* st = g_sin + pos * 48;
#pragma unroll
    for (int q3 = 0; q3 < 3; q3++) {
        int d = lane + q3 * 32;
        int f = (d < 48) ? d : d - 48;
        float rh = (d < 48) ? -sh[wid][d + 48] : sh[wid][d - 48];
        float val = sh[wid][d] * ct[f] + rh * st[f];
        x[d] = isK ? __uint_as_float(f2tf32(val)) : val;
    }
}

// ---------------------------------------------------------------------------
// Tensor-core flash attention v2.
// CTA = (128-query tile, head, batch), 256 threads / 8 warps.
// K-tile 64, cp.async double-buffered K/V (pre-rounded tf32 bits in gmem).
// Warp w owns query rows [16w,16w+16). Dedicated P region (no aliasing).
// Strides: Q/K 100 (mod32=4), V 136 (mod32=8), P 68 (mod32=4) - conflict-free.
// ---------------------------------------------------------------------------
#define QT128 128
#define KT64  64
#define QSTR 100
#define VSTR 136
#define PSTR 68
#define SM_QS   0                        // Qs [128][100] tf32
#define SM_KF   (128*QSTR)               // Kf [2][64][100]
#define SM_VF   (SM_KF + 2*64*QSTR)      // Vf [2][64][136]
#define SM_PS   (SM_VF + 2*64*VSTR)      // Ps [8][16][68]
#define ATTN_WORDS (SM_PS + 8*16*PSTR)   // 51712 words = 206848 B

extern __shared__ unsigned ds_attn[];

__global__ void __launch_bounds__(256) attn_tc_kernel()
{
    const int qt  = blockIdx.x;       // 0..15
    const int h   = blockIdx.y;
    const int b   = blockIdx.z;
    const int kvh = h >> 2;
    const int tid = threadIdx.x;
    const int w   = tid >> 5;
    const int lane = tid & 31;
    const int g   = lane >> 2;
    const int t   = lane & 3;
    const int wm  = w * 16;

    unsigned* Qs  = ds_attn + SM_QS;
    unsigned* Psw = ds_attn + SM_PS + w * 16 * PSTR;
    unsigned kf_s[2], vf_s[2];
    kf_s[0] = (unsigned)__cvta_generic_to_shared(ds_attn + SM_KF);
    kf_s[1] = kf_s[0] + 64 * QSTR * 4;
    vf_s[0] = (unsigned)__cvta_generic_to_shared(ds_attn + SM_VF);
    vf_s[1] = vf_s[0] + 64 * VSTR * 4;
    unsigned* Kf[2] = { ds_attn + SM_KF, ds_attn + SM_KF + 64 * QSTR };
    unsigned* Vf[2] = { ds_attn + SM_VF, ds_attn + SM_VF + 64 * VSTR };

    const float scale = 1.0f / sqrtf(96.0f);
    const float* kb0 = g_k + (size_t)(b * S_) * KN + kvh * KQD_;
    const float* vb0 = g_v + (size_t)(b * S_) * VN + kvh * VD_;

    // Load Q tile once (scaled, tf32)
    const float* qbase = g_q + ((size_t)(b * S_ + qt * QT128)) * QN + h * KQD_;
    for (int it = tid; it < 128 * 24; it += 256) {
        int r = it / 24, c4 = (it % 24) * 4;
        float4 v = *(const float4*)(qbase + (size_t)r * QN + c4);
        uint4 u = make_uint4(f2tf32(v.x * scale), f2tf32(v.y * scale),
                             f2tf32(v.z * scale), f2tf32(v.w * scale));
        *(uint4*)&Qs[r * QSTR + c4] = u;
    }

    // Prologue: async-load tile 0
    {
        const float* kbase = kb0 + (size_t)0;
        for (int it = tid; it < 64 * 24; it += 256) {
            int r = it / 24, c4 = (it % 24) * 4;
            cp_async16(kf_s[0] + (r * QSTR + c4) * 4, kbase + (size_t)r * KN + c4);
        }
        const float* vbase = vb0;
        for (int it = tid; it < 64 * 32; it += 256) {
            int r = it >> 5, c4 = (it & 31) * 4;
            cp_async16(vf_s[0] + (r * VSTR + c4) * 4, vbase + (size_t)r * VN + c4);
        }
        CP_COMMIT();
    }

    float o[16][4];
#pragma unroll
    for (int j = 0; j < 16; j++)
#pragma unroll
        for (int r = 0; r < 4; r++) o[j][r] = 0.f;
    float m0 = -INFINITY, m1 = -INFINITY, l0 = 0.f, l1 = 0.f;

    const int row0g = qt * QT128 + wm + g;
    const int row1g = row0g + 8;
    const int kt_max = 2 * qt + 1;

    for (int kt = 0; kt <= kt_max; kt++) {
        const int cur = kt & 1;
        // issue next tile
        if (kt < kt_max) {
            const int nb = (kt + 1) & 1;
            const float* kbase = kb0 + (size_t)(kt + 1) * KT64 * KN;
            for (int it = tid; it < 64 * 24; it += 256) {
                int r = it / 24, c4 = (it % 24) * 4;
                cp_async16(kf_s[nb] + (r * QSTR + c4) * 4, kbase + (size_t)r * KN + c4);
            }
            const float* vbase = vb0 + (size_t)(kt + 1) * KT64 * VN;
            for (int it = tid; it < 64 * 32; it += 256) {
                int r = it >> 5, c4 = (it & 31) * 4;
                cp_async16(vf_s[nb] + (r * VSTR + c4) * 4, vbase + (size_t)r * VN + c4);
            }
        }
        CP_COMMIT();
        CP_WAIT1();
        __syncthreads();

        // skip tiles fully above this warp's rows
        if (KT64 * kt <= qt * QT128 + wm + 15) {
            const unsigned* Kc = Kf[cur];
            const unsigned* Vc = Vf[cur];

            // S = Q K^T (16x64, K-dim 96)
            float s[8][4];
#pragma unroll
            for (int j = 0; j < 8; j++)
#pragma unroll
                for (int r = 0; r < 4; r++) s[j][r] = 0.f;
#pragma unroll
            for (int k8 = 0; k8 < 96; k8 += 8) {
                unsigned af[4];
                af[0] = Qs[(wm + g    ) * QSTR + k8 + t    ];
                af[1] = Qs[(wm + g + 8) * QSTR + k8 + t    ];
                af[2] = Qs[(wm + g    ) * QSTR + k8 + t + 4];
                af[3] = Qs[(wm + g + 8) * QSTR + k8 + t + 4];
#pragma unroll
                for (int j = 0; j < 8; j++) {
                    unsigned bf[2];
                    bf[0] = Kc[(8 * j + g) * QSTR + k8 + t    ];
                    bf[1] = Kc[(8 * j + g) * QSTR + k8 + t + 4];
                    mma_tf32(s[j], af, bf);
                }
            }

            if (kt >= 2 * qt) {   // diagonal band
#pragma unroll
                for (int j = 0; j < 8; j++) {
                    int c0 = kt * KT64 + 8 * j + 2 * t;
                    if (c0     > row0g) s[j][0] = -INFINITY;
                    if (c0 + 1 > row0g) s[j][1] = -INFINITY;
                    if (c0     > row1g) s[j][2] = -INFINITY;
                    if (c0 + 1 > row1g) s[j][3] = -INFINITY;
                }
            }

            // online softmax
            float ml0 = -INFINITY, ml1 = -INFINITY;
#pragma unroll
            for (int j = 0; j < 8; j++) {
                ml0 = fmaxf(ml0, fmaxf(s[j][0], s[j][1]));
                ml1 = fmaxf(ml1, fmaxf(s[j][2], s[j][3]));
            }
            ml0 = fmaxf(ml0, __shfl_xor_sync(0xffffffffu, ml0, 1));
            ml0 = fmaxf(ml0, __shfl_xor_sync(0xffffffffu, ml0, 2));
            ml1 = fmaxf(ml1, __shfl_xor_sync(0xffffffffu, ml1, 1));
            ml1 = fmaxf(ml1, __shfl_xor_sync(0xffffffffu, ml1, 2));
            float mn0 = fmaxf(m0, ml0), mn1 = fmaxf(m1, ml1);
            float al0 = __expf(m0 - mn0), al1 = __expf(m1 - mn1);
            m0 = mn0; m1 = mn1;
            float sum0 = 0.f, sum1 = 0.f;
#pragma unroll
            for (int j = 0; j < 8; j++) {
                s[j][0] = __expf(s[j][0] - mn0); sum0 += s[j][0];
                s[j][1] = __expf(s[j][1] - mn0); sum0 += s[j][1];
                s[j][2] = __expf(s[j][2] - mn1); sum1 += s[j][2];
                s[j][3] = __expf(s[j][3] - mn1); sum1 += s[j][3];
            }
            sum0 += __shfl_xor_sync(0xffffffffu, sum0, 1);
            sum0 += __shfl_xor_sync(0xffffffffu, sum0, 2);
            sum1 += __shfl_xor_sync(0xffffffffu, sum1, 1);
            sum1 += __shfl_xor_sync(0xffffffffu, sum1, 2);
            l0 = l0 * al0 + sum0;
            l1 = l1 * al1 + sum1;
#pragma unroll
            for (int j = 0; j < 16; j++) {
                o[j][0] *= al0; o[j][1] *= al0;
                o[j][2] *= al1; o[j][3] *= al1;
            }

            // store P (per-warp region; warp-local sync only)
#pragma unroll
            for (int j = 0; j < 8; j++) {
                *(uint2*)&Psw[g * PSTR + 8 * j + 2 * t] =
                    make_uint2(f2tf32(s[j][0]), f2tf32(s[j][1]));
                *(uint2*)&Psw[(g + 8) * PSTR + 8 * j + 2 * t] =
                    make_uint2(f2tf32(s[j][2]), f2tf32(s[j][3]));
            }
            __syncwarp();

            // O += P V (16x128, K-dim 64)
#pragma unroll
            for (int k8 = 0; k8 < 64; k8 += 8) {
                unsigned af[4];
                af[0] = Psw[(g    ) * PSTR + k8 + t    ];
                af[1] = Psw[(g + 8) * PSTR + k8 + t    ];
                af[2] = Psw[(g    ) * PSTR + k8 + t + 4];
                af[3] = Psw[(g + 8) * PSTR + k8 + t + 4];
#pragma unroll
                for (int jn = 0; jn < 16; jn++) {
                    unsigned bf[2];
                    bf[0] = Vc[(k8 + t    ) * VSTR + 8 * jn + g];
                    bf[1] = Vc[(k8 + t + 4) * VSTR + 8 * jn + g];
                    mma_tf32(o[jn], af, bf);
                }
            }
        }
        __syncthreads();   // all warps done with buf before it is refilled
    }

    // Epilogue
    float inv0 = 1.0f / l0, inv1 = 1.0f / l1;
    float* ob = g_ao + ((size_t)(b * S_)) * ON + h * VD_;
    size_t r0 = (size_t)(qt * QT128 + wm + g);
    size_t r1 = r0 + 8;
#pragma unroll
    for (int jn = 0; jn < 16; jn++) {
        int col = 8 * jn + 2 * t;
        *(float2*)&ob[r0 * ON + col] = make_float2(o[jn][0] * inv0, o[jn][1] * inv0);
        *(float2*)&ob[r1 * ON + col] = make_float2(o[jn][2] * inv1, o[jn][3] * inv1);
    }
}

// ---------------------------------------------------------------------------
extern "C" void kernel_launch(void* const* d_in, const int* in_sizes, int n_in,
                              void* d_out, int out_size)
{
    const float* hidden = (const float*)d_in[0];
    const int*   pos    = (const int*)  d_in[1];
    const float* Wq     = (const float*)d_in[2];
    const float* Wk     = (const float*)d_in[3];
    const float* Wv     = (const float*)d_in[4];
    const float* Wo     = (const float*)d_in[5];
    const float* qw     = (const float*)d_in[6];
    const float* kw     = (const float*)d_in[7];
    float* out = (float*)d_out;

    void *pq, *pk, *pv, *pa;
    cudaGetSymbolAddress(&pq, g_q);
    cudaGetSymbolAddress(&pk, g_k);
    cudaGetSymbolAddress(&pv, g_v);
    cudaGetSymbolAddress(&pa, g_ao);
    float* qb = (float*)pq;
    float* kb = (float*)pk;
    float* vb = (float*)pv;
    float* ab = (float*)pa;

    static int smem_set = 0;
    if (!smem_set) {
        cudaFuncSetAttribute(attn_tc_kernel,
                             cudaFuncAttributeMaxDynamicSharedMemorySize,
                             ATTN_WORDS * 4);
        smem_set = 1;
    }

    // 1. RoPE table
    rope_table_kernel<<<(S_ * 48 + 255) / 256, 256>>>();

    // 2. Fused QKV projection (tf32 TC; V output pre-rounded to tf32 bits)
    sgemm_qkv<<<dim3(QN / 128, TOK / 128, 3), 256>>>(hidden, Wq, Wk, Wv, qb, kb, vb);

    // 3. Fused RMSNorm + RoPE (Q plain fp32; K pre-rounded to tf32 bits)
    rmsnorm_rope_fused<<<(QROWS + KROWS) / 4, 128>>>(qb, kb, qw, kw, pos);

    // 4. Tensor-core flash attention (pipelined, 128-q tiles)
    attn_tc_kernel<<<dim3(S_ / QT128, H_, B_), 256, ATTN_WORDS * 4>>>();

    // 5. Output projection
    sgemm_tf32<<<dim3(D_ / 128, TOK / 128), 256>>>(ab, Wo, out, TOK, D_, ON);
}